// round 8
// baseline (speedup 1.0000x reference)
#include <cuda_runtime.h>
#include <math.h>

#define NUM_B 8
#define NUM_A 131072
#define NUM_C 4
#define NUM_M 64
#define BLOCK 256
#define APT 8                               // anchors per thread (2 passes x 4)
#define GRIDX (NUM_A / (BLOCK * APT))       // 64
#define NBLOCKS (GRIDX * NUM_B)             // 512 = ONE wave (148 SMs x 4 blocks = 592)
#define TPS (GRIDX * BLOCK)                 // 16384 threads per sample

// Per-block partials: [cls_sum, xy_sum, ang_sum, num_pos]. Plain stores each run.
__device__ float4 g_part[NBLOCKS];
__device__ unsigned int g_count = 0;   // self-resetting completion counter

#define ADD_F32X2(out, a, b) \
    asm("add.rn.f32x2 %0, %1, %2;" : "=l"(out) : "l"(a), "l"(b))
#define MUL_F32X2(out, a, b) \
    asm("mul.rn.f32x2 %0, %1, %2;" : "=l"(out) : "l"(a), "l"(b))
#define FMA_F32X2(out, a, b, c) \
    asm("fma.rn.f32x2 %0, %1, %2, %3;" : "=l"(out) : "l"(a), "l"(b), "l"(c))
#define PACK_F32X2(out, lo, hi) \
    asm("mov.b64 %0, {%1, %2};" : "=l"(out) : "r"(lo), "r"(hi))

__global__ __launch_bounds__(BLOCK, 4) void focal_fused_kernel(
    const float* __restrict__ cls,   // (B, A, C)
    const float* __restrict__ reg,   // (B, A, 3)
    const float* __restrict__ anc,   // (A, 3)
    const float* __restrict__ ann,   // (B, M, 4)
    float* __restrict__ out)         // (3,)
{
    // Pair-of-structs, NEGATED coords: float4 j = (-x_{2j}, -x_{2j+1}, -y_{2j}, -y_{2j+1})
    __shared__ __align__(16) float s_pair[NUM_M * 2];
    __shared__ float s_al[NUM_M];
    __shared__ float s_lb[NUM_M];

    const int b   = blockIdx.y;
    const int tid = threadIdx.x;

    if (tid < NUM_M) {
        const float* a4 = ann + ((size_t)b * NUM_M + tid) * 4;
        float x = a4[0], y = a4[1], al = a4[2], lb = a4[3];
        bool valid = (lb != -1.0f);
        // invalid -> coords pushed to -1e18: d2 ~ 1e36, never wins argmin,
        // never passes any threshold.
        const int j = tid >> 1, slot = tid & 1;
        s_pair[4 * j + slot]     = valid ? -x : -1e18f;
        s_pair[4 * j + 2 + slot] = valid ? -y : -1e18f;
        s_al[tid] = al;
        s_lb[tid] = lb;
    }
    __syncthreads();

    const int t = blockIdx.x * BLOCK + tid;   // thread index within sample
    float v0 = 0.0f, v1 = 0.0f, v2 = 0.0f, v3 = 0.0f;

    // Two passes of the proven 4-anchor routine (anchors t + (4*pass+k)*TPS).
    // Rolled loop: one code copy, register state reused -> stays <= 64 regs
    // so 4 blocks/SM and the whole grid is resident in one wave.
    #pragma unroll 1
    for (int pass = 0; pass < 2; pass++) {
        const int abase = t + pass * 4 * TPS;

        float ax[4], ay[4], aal[4];
        unsigned long long axx[4], ayy[4];
        float4 c4[4];
        float rx[4], ry[4], ra[4];

        #pragma unroll
        for (int k = 0; k < 4; k++) {
            const int a = abase + k * TPS;
            ax[k]  = anc[3 * a + 0];
            ay[k]  = anc[3 * a + 1];
            aal[k] = anc[3 * a + 2];
            c4[k] = *(const float4*)(cls + ((size_t)b * NUM_A + a) * NUM_C);
            const float* r3 = reg + ((size_t)b * NUM_A + a) * 3;
            rx[k] = r3[0]; ry[k] = r3[1]; ra[k] = r3[2];
            unsigned axb = __float_as_uint(ax[k]), ayb = __float_as_uint(ay[k]);
            PACK_F32X2(axx[k], axb, axb);
            PACK_F32X2(ayy[k], ayb, ayb);
        }

        // 64-way argmin via bit-packed keys (positive-float bits u32-ordered;
        // low 6 bits carry annotation index; ties -> lower index == argmin).
        unsigned int bestkey[4];
        #pragma unroll
        for (int k = 0; k < 4; k++) bestkey[k] = 0xffffffffu;
        const unsigned int KMASK = 0xffffffc0u;
        const ulonglong2* pq = (const ulonglong2*)s_pair;

        #pragma unroll
        for (int j = 0; j < NUM_M / 2; j++) {
            ulonglong2 q = pq[j];             // one LDS.128 feeds all 4 anchors
            const unsigned i0 = (unsigned)(2 * j), i1 = (unsigned)(2 * j + 1);
            #pragma unroll
            for (int k = 0; k < 4; k++) {
                unsigned long long dxp, dyp, tp, d2p;
                ADD_F32X2(dxp, axx[k], q.x);  // (ax-x0, ax-x1) (coords negated)
                ADD_F32X2(dyp, ayy[k], q.y);
                MUL_F32X2(tp, dxp, dxp);
                FMA_F32X2(d2p, dyp, dyp, tp); // == fmaf(dy,dy,dx*dx) per lane
                unsigned lo = (unsigned)d2p;
                unsigned hi = (unsigned)(d2p >> 32);
                unsigned key0 = (lo & KMASK) | i0;
                unsigned key1 = (hi & KMASK) | i1;
                bestkey[k] = min(bestkey[k], min(key0, key1));
            }
        }

        // ---- per-anchor epilogue ----
        #pragma unroll
        for (int k = 0; k < 4; k++) {
            const int bestm = (int)(bestkey[k] & 63u);
            const int bj = bestm >> 1, bslot = bestm & 1;
            const float bx  = -s_pair[4 * bj + bslot];
            const float by  = -s_pair[4 * bj + 2 + bslot];
            const float bal = s_al[bestm];
            const float ddx = ax[k] - bx;
            const float ddy = ay[k] - by;
            const float best = fmaf(ddy, ddy, ddx * ddx);   // exact winner d2
            const float dang = fabsf(aal[k] - bal);

            // sqrt-free thresholds: dxy<20 <=> d2<400 ; dxy>=30 <=> d2>=900
            const bool positive   = (best < 400.0f) && (dang < 15.0f);
            const bool background = (best >= 900.0f) || (dang >= 22.5f);
            const bool care       = positive || background;

            if (care) {
                int label = positive ? min(max((int)s_lb[bestm], 0), NUM_C - 1) : -1;
                float cv[4] = {c4[k].x, c4[k].y, c4[k].z, c4[k].w};
                #pragma unroll
                for (int c = 0; c < NUM_C; c++) {
                    float p = fminf(fmaxf(cv[c], 1e-4f), 1.0f - 1e-4f);
                    bool is1 = (c == label);
                    // t==1: w = 0.95*(1-p)^2, bce = -log(p)
                    // t==0: w = 0.05*p^2,     bce = -log(1-p)
                    float q = is1 ? (1.0f - p) : p;
                    float w = (is1 ? 0.95f : 0.05f) * q * q;
                    float bce = -__logf(1.0f - q);
                    v0 = fmaf(w, bce, v0);
                }
            }

            if (positive) {
                float tx = bx  - ax[k];
                float ty = by  - ay[k];
                float ta = bal - aal[k];
                float dxr = fabsf(tx - rx[k]);
                float dyr = fabsf(ty - ry[k]);
                const float inv9 = 1.0f / 9.0f;
                float lx = (dxr <= inv9) ? (4.5f * dxr * dxr) : (dxr - 0.5f * inv9);
                float ly = (dyr <= inv9) ? (4.5f * dyr * dyr) : (dyr - 0.5f * inv9);
                v1 += lx + ly;
                v2 += fmaxf((fabsf(ta - ra[k]) - 10.0f) * 0.2f, 0.0f);
                v3 += 1.0f;
            }
        }
    }

    // ---- block reduction: 4 quantities ----
    #pragma unroll
    for (int o = 16; o > 0; o >>= 1) {
        v0 += __shfl_down_sync(0xffffffffu, v0, o);
        v1 += __shfl_down_sync(0xffffffffu, v1, o);
        v2 += __shfl_down_sync(0xffffffffu, v2, o);
        v3 += __shfl_down_sync(0xffffffffu, v3, o);
    }
    __shared__ float red[BLOCK / 32][4];
    const int wid = tid >> 5, lid = tid & 31;
    if (lid == 0) {
        red[wid][0] = v0; red[wid][1] = v1; red[wid][2] = v2; red[wid][3] = v3;
    }
    __syncthreads();
    if (tid < 4) {
        float s = 0.0f;
        #pragma unroll
        for (int w = 0; w < BLOCK / 32; w++) s += red[w][tid];
        ((float*)&g_part[(size_t)b * GRIDX + blockIdx.x])[tid] = s;
        __threadfence();   // publish partials before the ticket increment
    }
    __syncthreads();

    // ---- last-block finalize (fused, no extra launches) ----
    __shared__ bool is_last;
    if (tid == 0) {
        unsigned v = atomicAdd(&g_count, 1u);
        is_last = (v == NBLOCKS - 1);
    }
    __syncthreads();
    if (!is_last) return;
    if (tid == 0) g_count = 0;   // reset for next graph replay

    // 8 warps: warp w reduces sample b=w over its 64 partials.
    __shared__ float s_res[NUM_B][3];
    const int w = tid >> 5, l = tid & 31;
    float4 acc = make_float4(0.f, 0.f, 0.f, 0.f);
    #pragma unroll
    for (int kk = 0; kk < GRIDX / 32; kk++) {
        float4 p = g_part[(size_t)w * GRIDX + l + 32 * kk];
        acc.x += p.x; acc.y += p.y; acc.z += p.z; acc.w += p.w;
    }
    #pragma unroll
    for (int o = 16; o > 0; o >>= 1) {
        acc.x += __shfl_down_sync(0xffffffffu, acc.x, o);
        acc.y += __shfl_down_sync(0xffffffffu, acc.y, o);
        acc.z += __shfl_down_sync(0xffffffffu, acc.z, o);
        acc.w += __shfl_down_sync(0xffffffffu, acc.w, o);
    }
    if (l == 0) {
        float denom = fmaxf(acc.w, 1.0f);
        s_res[w][0] = acc.x / denom;
        s_res[w][1] = acc.y / (2.0f * denom);
        s_res[w][2] = acc.z / denom;
    }
    __syncthreads();
    if (tid == 0) {
        float c = 0.f, x = 0.f, an = 0.f;
        #pragma unroll
        for (int bb = 0; bb < NUM_B; bb++) {
            c += s_res[bb][0]; x += s_res[bb][1]; an += s_res[bb][2];
        }
        out[0] = c  * (1.0f / NUM_B);
        out[1] = x  * (1.0f / NUM_B);
        out[2] = an * (1.0f / NUM_B);
    }
}

extern "C" void kernel_launch(void* const* d_in, const int* in_sizes, int n_in,
                              void* d_out, int out_size) {
    (void)in_sizes; (void)n_in; (void)out_size;
    const float* cls = (const float*)d_in[0];   // (B, A, C)
    const float* reg = (const float*)d_in[1];   // (B, A, 3)
    const float* anc = (const float*)d_in[2];   // (1, A, 3)
    const float* ann = (const float*)d_in[3];   // (B, M, 4)
    float* out = (float*)d_out;

    dim3 grid(GRIDX, NUM_B);
    focal_fused_kernel<<<grid, BLOCK>>>(cls, reg, anc, ann, out);
}

// round 9
// speedup vs baseline: 2.0570x; 2.0570x over previous
#include <cuda_runtime.h>
#include <math.h>

#define NUM_B 8
#define NUM_A 131072
#define NUM_C 4
#define NUM_M 64
#define BLOCK 256
#define APT 4                               // anchors per thread, CONTIGUOUS
#define GRIDX (NUM_A / (BLOCK * APT))       // 128
#define NBLOCKS (GRIDX * NUM_B)             // 1024

// Per-block partials: [cls_sum, xy_sum, ang_sum, num_pos]. Plain stores each run.
__device__ float4 g_part[NBLOCKS];
__device__ unsigned int g_count = 0;   // self-resetting completion counter

#define ADD_F32X2(out, a, b) \
    asm("add.rn.f32x2 %0, %1, %2;" : "=l"(out) : "l"(a), "l"(b))
#define MUL_F32X2(out, a, b) \
    asm("mul.rn.f32x2 %0, %1, %2;" : "=l"(out) : "l"(a), "l"(b))
#define FMA_F32X2(out, a, b, c) \
    asm("fma.rn.f32x2 %0, %1, %2, %3;" : "=l"(out) : "l"(a), "l"(b), "l"(c))
#define PACK_F32X2(out, lo, hi) \
    asm("mov.b64 %0, {%1, %2};" : "=l"(out) : "r"(lo), "r"(hi))

__global__ __launch_bounds__(BLOCK, 5) void focal_fused_kernel(
    const float* __restrict__ cls,   // (B, A, C)
    const float* __restrict__ reg,   // (B, A, 3)
    const float* __restrict__ anc,   // (A, 3)
    const float* __restrict__ ann,   // (B, M, 4)
    float* __restrict__ out)         // (3,)
{
    // Pair-of-structs, NEGATED coords: float4 j = (-x_{2j}, -x_{2j+1}, -y_{2j}, -y_{2j+1})
    __shared__ __align__(16) float s_pair[NUM_M * 2];
    __shared__ float s_al[NUM_M];
    __shared__ float s_lb[NUM_M];

    const int b   = blockIdx.y;
    const int tid = threadIdx.x;

    if (tid < NUM_M) {
        const float* a4 = ann + ((size_t)b * NUM_M + tid) * 4;
        float x = a4[0], y = a4[1], al = a4[2], lb = a4[3];
        bool valid = (lb != -1.0f);
        // invalid -> coords pushed to -1e18: d2 ~ 1e36, never wins argmin,
        // never passes any threshold.
        const int j = tid >> 1, slot = tid & 1;
        s_pair[4 * j + slot]     = valid ? -x : -1e18f;
        s_pair[4 * j + 2 + slot] = valid ? -y : -1e18f;
        s_al[tid] = al;
        s_lb[tid] = lb;
    }
    __syncthreads();

    // 4 CONTIGUOUS anchors per thread: a = 4*th .. 4*th+3. All per-anchor
    // gmem rows become aligned float4 loads.
    const int th = blockIdx.x * BLOCK + tid;       // 0..32767 within sample

    // ---- anchor coords: 3 x LDG.128 (12 floats = 4 anchors x (x,y,alpha)) ----
    float ax[APT], ay[APT], aal[APT];
    {
        const float4* p = (const float4*)(anc + (size_t)th * 12);
        float4 A0 = p[0], A1 = p[1], A2 = p[2];
        ax[0] = A0.x; ay[0] = A0.y; aal[0] = A0.z;
        ax[1] = A0.w; ay[1] = A1.x; aal[1] = A1.y;
        ax[2] = A1.z; ay[2] = A1.w; aal[2] = A2.x;
        ax[3] = A2.y; ay[3] = A2.z; aal[3] = A2.w;
    }
    unsigned long long axx[APT], ayy[APT];
    #pragma unroll
    for (int k = 0; k < APT; k++) {
        unsigned axb = __float_as_uint(ax[k]), ayb = __float_as_uint(ay[k]);
        PACK_F32X2(axx[k], axb, axb);
        PACK_F32X2(ayy[k], ayb, ayb);
    }

    // ---- 64-way argmin via bit-packed keys ----
    // (positive-float bits are u32-ordered; low 6 bits carry the annotation
    //  index; ties -> lower index, matching jnp.argmin first-index semantics)
    unsigned int bestkey[APT];
    #pragma unroll
    for (int k = 0; k < APT; k++) bestkey[k] = 0xffffffffu;
    const unsigned int KMASK = 0xffffffc0u;
    const ulonglong2* pq = (const ulonglong2*)s_pair;

    #pragma unroll
    for (int j = 0; j < NUM_M / 2; j++) {
        ulonglong2 q = pq[j];                 // one LDS.128 feeds all 4 anchors
        const unsigned i0 = (unsigned)(2 * j), i1 = (unsigned)(2 * j + 1);
        #pragma unroll
        for (int k = 0; k < APT; k++) {
            unsigned long long dxp, dyp, tp, d2p;
            ADD_F32X2(dxp, axx[k], q.x);      // (ax-x0, ax-x1) (coords negated)
            ADD_F32X2(dyp, ayy[k], q.y);
            MUL_F32X2(tp, dxp, dxp);
            FMA_F32X2(d2p, dyp, dyp, tp);     // == fmaf(dy,dy,dx*dx) per lane
            unsigned lo = (unsigned)d2p;
            unsigned hi = (unsigned)(d2p >> 32);
            unsigned key0 = (lo & KMASK) | i0;
            unsigned key1 = (hi & KMASK) | i1;
            bestkey[k] = min(bestkey[k], min(key0, key1));
        }
    }

    // ---- cold loads, deferred past the hot loop (keeps loop regs lean) ----
    float4 c4[APT];
    {
        const float4* p = (const float4*)(cls + ((size_t)b * NUM_A + (size_t)th * 4) * NUM_C);
        c4[0] = p[0]; c4[1] = p[1]; c4[2] = p[2]; c4[3] = p[3];
    }
    float rx[APT], ry[APT], ra[APT];
    {
        const float4* p = (const float4*)(reg + ((size_t)b * NUM_A) * 3 + (size_t)th * 12);
        float4 R0 = p[0], R1 = p[1], R2 = p[2];
        rx[0] = R0.x; ry[0] = R0.y; ra[0] = R0.z;
        rx[1] = R0.w; ry[1] = R1.x; ra[1] = R1.y;
        rx[2] = R1.z; ry[2] = R1.w; ra[2] = R2.x;
        rx[3] = R2.y; ry[3] = R2.z; ra[3] = R2.w;
    }

    // ---- per-anchor epilogue ----
    float v0 = 0.0f, v1 = 0.0f, v2 = 0.0f, v3 = 0.0f;
    #pragma unroll
    for (int k = 0; k < APT; k++) {
        const int bestm = (int)(bestkey[k] & 63u);
        const int bj = bestm >> 1, bslot = bestm & 1;
        const float bx  = -s_pair[4 * bj + bslot];
        const float by  = -s_pair[4 * bj + 2 + bslot];
        const float bal = s_al[bestm];
        const float ddx = ax[k] - bx;
        const float ddy = ay[k] - by;
        const float best = fmaf(ddy, ddy, ddx * ddx);   // exact winner d2
        const float dang = fabsf(aal[k] - bal);

        // sqrt-free thresholds: dxy<20 <=> d2<400 ; dxy>=30 <=> d2>=900
        const bool positive   = (best < 400.0f) && (dang < 15.0f);
        const bool background = (best >= 900.0f) || (dang >= 22.5f);
        const bool care       = positive || background;

        if (care) {
            int label = positive ? min(max((int)s_lb[bestm], 0), NUM_C - 1) : -1;
            float cv[4] = {c4[k].x, c4[k].y, c4[k].z, c4[k].w};
            #pragma unroll
            for (int c = 0; c < NUM_C; c++) {
                float p = fminf(fmaxf(cv[c], 1e-4f), 1.0f - 1e-4f);
                bool is1 = (c == label);
                // t==1: w = 0.95*(1-p)^2, bce = -log(p)
                // t==0: w = 0.05*p^2,     bce = -log(1-p)
                float q = is1 ? (1.0f - p) : p;
                float w = (is1 ? 0.95f : 0.05f) * q * q;
                float bce = -__logf(1.0f - q);
                v0 = fmaf(w, bce, v0);
            }
        }

        if (positive) {
            float tx = bx  - ax[k];
            float ty = by  - ay[k];
            float ta = bal - aal[k];
            float dxr = fabsf(tx - rx[k]);
            float dyr = fabsf(ty - ry[k]);
            const float inv9 = 1.0f / 9.0f;
            float lx = (dxr <= inv9) ? (4.5f * dxr * dxr) : (dxr - 0.5f * inv9);
            float ly = (dyr <= inv9) ? (4.5f * dyr * dyr) : (dyr - 0.5f * inv9);
            v1 += lx + ly;
            v2 += fmaxf((fabsf(ta - ra[k]) - 10.0f) * 0.2f, 0.0f);
            v3 += 1.0f;
        }
    }

    // ---- block reduction: 4 quantities ----
    #pragma unroll
    for (int o = 16; o > 0; o >>= 1) {
        v0 += __shfl_down_sync(0xffffffffu, v0, o);
        v1 += __shfl_down_sync(0xffffffffu, v1, o);
        v2 += __shfl_down_sync(0xffffffffu, v2, o);
        v3 += __shfl_down_sync(0xffffffffu, v3, o);
    }
    __shared__ float red[BLOCK / 32][4];
    const int wid = tid >> 5, lid = tid & 31;
    if (lid == 0) {
        red[wid][0] = v0; red[wid][1] = v1; red[wid][2] = v2; red[wid][3] = v3;
    }
    __syncthreads();
    if (tid < 4) {
        float s = 0.0f;
        #pragma unroll
        for (int w = 0; w < BLOCK / 32; w++) s += red[w][tid];
        ((float*)&g_part[(size_t)b * GRIDX + blockIdx.x])[tid] = s;
        __threadfence();   // publish partials before the ticket increment
    }
    __syncthreads();

    // ---- last-block finalize (fused, no extra launches) ----
    __shared__ bool is_last;
    if (tid == 0) {
        unsigned v = atomicAdd(&g_count, 1u);
        is_last = (v == NBLOCKS - 1);
    }
    __syncthreads();
    if (!is_last) return;
    if (tid == 0) g_count = 0;   // reset for next graph replay

    // 8 warps: warp w reduces sample b=w over its 128 partials.
    __shared__ float s_res[NUM_B][3];
    const int w = tid >> 5, l = tid & 31;
    float4 acc = make_float4(0.f, 0.f, 0.f, 0.f);
    #pragma unroll
    for (int kk = 0; kk < GRIDX / 32; kk++) {
        float4 p = g_part[(size_t)w * GRIDX + l + 32 * kk];
        acc.x += p.x; acc.y += p.y; acc.z += p.z; acc.w += p.w;
    }
    #pragma unroll
    for (int o = 16; o > 0; o >>= 1) {
        acc.x += __shfl_down_sync(0xffffffffu, acc.x, o);
        acc.y += __shfl_down_sync(0xffffffffu, acc.y, o);
        acc.z += __shfl_down_sync(0xffffffffu, acc.z, o);
        acc.w += __shfl_down_sync(0xffffffffu, acc.w, o);
    }
    if (l == 0) {
        float denom = fmaxf(acc.w, 1.0f);
        s_res[w][0] = acc.x / denom;
        s_res[w][1] = acc.y / (2.0f * denom);
        s_res[w][2] = acc.z / denom;
    }
    __syncthreads();
    if (tid == 0) {
        float c = 0.f, x = 0.f, an = 0.f;
        #pragma unroll
        for (int bb = 0; bb < NUM_B; bb++) {
            c += s_res[bb][0]; x += s_res[bb][1]; an += s_res[bb][2];
        }
        out[0] = c  * (1.0f / NUM_B);
        out[1] = x  * (1.0f / NUM_B);
        out[2] = an * (1.0f / NUM_B);
    }
}

extern "C" void kernel_launch(void* const* d_in, const int* in_sizes, int n_in,
                              void* d_out, int out_size) {
    (void)in_sizes; (void)n_in; (void)out_size;
    const float* cls = (const float*)d_in[0];   // (B, A, C)
    const float* reg = (const float*)d_in[1];   // (B, A, 3)
    const float* anc = (const float*)d_in[2];   // (1, A, 3)
    const float* ann = (const float*)d_in[3];   // (B, M, 4)
    float* out = (float*)d_out;

    dim3 grid(GRIDX, NUM_B);
    focal_fused_kernel<<<grid, BLOCK>>>(cls, reg, anc, ann, out);
}